// round 17
// baseline (speedup 1.0000x reference)
#include <cuda_runtime.h>
#include <cuda_bf16.h>
#include <math.h>
#include <stdint.h>

#define EXER_N 10000
#define STU_N  20000
#define DD     128
#define HH     3
#define HD     384
#define CAP    96
#define BATCH  2048

#define SZF(x) ((size_t)(x))

// ---------------- scratch arena ---------------------------------------------
static constexpr size_t O_Wz3   = 0;
static constexpr size_t O_Wzc   = O_Wz3   + SZF(5)*DD*HD;
static constexpr size_t O_Wlr   = O_Wzc   + SZF(5)*DD*DD;
static constexpr size_t O_bz    = O_Wlr   + SZF(5)*DD*8;
static constexpr size_t O_zE    = O_bz    + SZF(5)*DD;
static constexpr size_t O_elE   = O_zE    + SZF(3)*EXER_N*DD;
static constexpr size_t O_zlE   = O_elE   + SZF(3)*EXER_N*4;
static constexpr size_t O_erD   = O_zlE   + SZF(3)*EXER_N;
static constexpr size_t O_zrD   = O_erD   + SZF(EXER_N)*4;
static constexpr size_t O_ABCD  = O_zrD   + SZF(EXER_N);
static constexpr size_t O_ABPCD = O_ABCD  + SZF(STU_N)*4*DD;
static constexpr size_t O_stu1  = O_ABPCD + SZF(STU_N)*4*DD;
static constexpr size_t O_stu1p = O_stu1  + SZF(STU_N)*DD;
static constexpr size_t O_XYX   = O_stu1p + SZF(STU_N)*DD;
static constexpr size_t O_XYP   = O_XYX   + SZF(STU_N)*2*DD;
static constexpr size_t O_stu2  = O_XYP   + SZF(STU_N)*2*DD;
static constexpr size_t O_stu2p = O_stu2  + SZF(STU_N)*DD;
static constexpr size_t O_nb    = O_stu2p + SZF(STU_N)*DD;
static constexpr size_t O_nbp   = O_nb    + SZF(BATCH)*DD;
static constexpr size_t O_S     = O_nbp   + SZF(BATCH)*DD;
static constexpr size_t O_lossd = O_S     + DD;
static constexpr size_t O_part  = O_lossd + 16;
static constexpr size_t O_lpart = O_part  + SZF(16)*DD;
static constexpr size_t O_SCR   = O_lpart + BATCH;
static constexpr size_t SC_zS3  = 0;
static constexpr size_t SC_TOT  = SC_zS3 + SZF(STU_N)*HD;
static constexpr size_t F_TOT   = O_SCR + 4*SC_TOT;

static constexpr size_t OH_zE3  = 0;
static constexpr size_t OH_zE   = OH_zE3 + SZF(3)*EXER_N*HD;
static constexpr size_t H_TOT   = OH_zE  + SZF(3)*EXER_N*DD;

static constexpr size_t OI_adj  = 0;
static constexpr size_t OI_cnt  = SZF(3)*STU_N*CAP;
static constexpr size_t I_TOT   = OI_cnt + SZF(3)*STU_N;

__device__ __align__(256) float          g_farena[F_TOT];
__device__ __align__(256) __nv_bfloat16  g_harena[H_TOT];
__device__ __align__(256) int            g_iarena[I_TOT];

// ---------------- batched pointer structs ------------------------------------
struct GB {
    const float*    A[4];
    const float*    B[4];
    float*          C[4];
    float*          C2[4];
    __nv_bfloat16*  Ch[4];
    const float*    bias[4];
    const float*    addm[4];
};
struct EZB {
    const float* x[4];
    const float* wlr[4];
    const float* z[4];
    const float* aW[4];
    float*       el[4];
    float*       er[4];
    float*       zl[4];
    float*       zr[4];
};
struct FZB {
    const int*           adj[4];
    const int*           cnt[4];
    const float*         x[4];
    const float*         wlr[4];
    const float*         elE[4];
    const __nv_bfloat16* zE3[4];
    const float*         zS3[4];
    const __nv_bfloat16* zE[4];
    const float*         zlE[4];
    const float*         bz[4];
    const float*         aW[4];
    float*               out[4];
    float*               out2[4];
};
struct FZM {
    const int*           adj[2];
    const int*           cnt[2];
    const float*         wlr[2];
    const float*         elE[2];
    const __nv_bfloat16* zE3[2];
    const __nv_bfloat16* zE[2];
    const float*         zlE[2];
    const float*         bz[2];
    const float*         aW[2];
    const float*         xX[2];
    const float*         xP[2];
    const float*         zS3X[2];
    const float*         zS3P[2];
    float*               outX[2];
    float*               outP[2];
};
struct ADJB {
    const int* src[3];
    const int* dst[3];
    int        ecnt[3];
    int*       adj[3];
    int*       cnt[3];
};
struct NRB {
    const float* emb[2];
    float*       out[2];
};

// ---------------- TF32 tensor-core batched GEMM (128x128, best config) -------
__device__ __forceinline__ uint32_t f2tf32(float x) {
    uint32_t u;
    asm("cvt.rna.tf32.f32 %0, %1;" : "=r"(u) : "f"(x));
    return u;
}
__device__ __forceinline__ void mma_tf32(float* c, uint32_t a0, uint32_t a1,
                                         uint32_t a2, uint32_t a3,
                                         uint32_t b0, uint32_t b1) {
    asm volatile(
        "mma.sync.aligned.m16n8k8.row.col.f32.tf32.tf32.f32 "
        "{%0,%1,%2,%3}, {%4,%5,%6,%7}, {%8,%9}, {%0,%1,%2,%3};"
        : "+f"(c[0]), "+f"(c[1]), "+f"(c[2]), "+f"(c[3])
        : "r"(a0), "r"(a1), "r"(a2), "r"(a3), "r"(b0), "r"(b1));
}

#define SPAD 136

__global__ __launch_bounds__(256, 2)
void tgemm_b(GB g, int lda, int ldc, int ldadd, int M, int N, int K)
{
    const int z = blockIdx.z;
    const float* __restrict__ A    = g.A[z];
    const float* __restrict__ B    = g.B[z];
    float*                    C    = g.C[z];
    float*                    C2   = g.C2[z];
    __nv_bfloat16*            Ch   = g.Ch[z];
    const float*              bias = g.bias[z];
    const float*              addm = g.addm[z];

    __shared__ uint32_t As[2][16][SPAD];
    __shared__ uint32_t Bs[2][16][SPAD];

    const int tid  = threadIdx.x;
    const int bm   = blockIdx.y * 128;
    const int bn   = blockIdx.x * 128;
    const int lane = tid & 31;
    const int gid  = lane >> 2;
    const int tg   = lane & 3;
    const int warp = tid >> 5;
    const int wm   = warp & 3;
    const int wn   = warp >> 2;

    float acc[2][8][4];
#pragma unroll
    for (int mt = 0; mt < 2; mt++)
#pragma unroll
        for (int nt = 0; nt < 8; nt++)
#pragma unroll
            for (int c = 0; c < 4; c++) acc[mt][nt][c] = 0.f;

    const int am  = tid >> 1;
    const int ak0 = (tid & 1) * 4;
    const int brr = tid >> 5;
    const int bcc = (tid & 31) * 4;

    const bool arow_ok = (bm + am < M);
    float4 av0, av1, bv0, bv1;

    auto ldtile = [&](int k0) {
        av0 = arow_ok ? *(const float4*)(A + (size_t)(bm + am) * lda + k0 + ak0)
                      : make_float4(0.f, 0.f, 0.f, 0.f);
        av1 = arow_ok ? *(const float4*)(A + (size_t)(bm + am) * lda + k0 + 8 + ak0)
                      : make_float4(0.f, 0.f, 0.f, 0.f);
        bv0 = *(const float4*)(B + (size_t)(k0 + brr) * N + bn + bcc);
        bv1 = *(const float4*)(B + (size_t)(k0 + 8 + brr) * N + bn + bcc);
    };
    auto sttile = [&](int p) {
        As[p][ak0 + 0][am] = f2tf32(av0.x);
        As[p][ak0 + 1][am] = f2tf32(av0.y);
        As[p][ak0 + 2][am] = f2tf32(av0.z);
        As[p][ak0 + 3][am] = f2tf32(av0.w);
        As[p][8 + ak0 + 0][am] = f2tf32(av1.x);
        As[p][8 + ak0 + 1][am] = f2tf32(av1.y);
        As[p][8 + ak0 + 2][am] = f2tf32(av1.z);
        As[p][8 + ak0 + 3][am] = f2tf32(av1.w);
        uint4 t0 = make_uint4(f2tf32(bv0.x), f2tf32(bv0.y), f2tf32(bv0.z), f2tf32(bv0.w));
        uint4 t1 = make_uint4(f2tf32(bv1.x), f2tf32(bv1.y), f2tf32(bv1.z), f2tf32(bv1.w));
        *(uint4*)(&Bs[p][brr][bcc]) = t0;
        *(uint4*)(&Bs[p][8 + brr][bcc]) = t1;
    };

    ldtile(0);
    sttile(0);

    const int nt_tiles = K / 16;
    for (int kt = 0; kt < nt_tiles; kt++) {
        const int p = kt & 1;
        const bool more = (kt + 1 < nt_tiles);
        if (more) ldtile((kt + 1) * 16);
        __syncthreads();

#pragma unroll
        for (int ks = 0; ks < 2; ks++) {
            const int kk = ks * 8;
            uint32_t bf[8][2];
#pragma unroll
            for (int nt = 0; nt < 8; nt++) {
                const int n0 = wn * 64 + nt * 8 + gid;
                bf[nt][0] = Bs[p][kk + tg][n0];
                bf[nt][1] = Bs[p][kk + tg + 4][n0];
            }
#pragma unroll
            for (int mt = 0; mt < 2; mt++) {
                const int m0 = wm * 32 + mt * 16;
                uint32_t a0 = As[p][kk + tg][m0 + gid];
                uint32_t a1 = As[p][kk + tg][m0 + gid + 8];
                uint32_t a2 = As[p][kk + tg + 4][m0 + gid];
                uint32_t a3 = As[p][kk + tg + 4][m0 + gid + 8];
#pragma unroll
                for (int nt = 0; nt < 8; nt++)
                    mma_tf32(acc[mt][nt], a0, a1, a2, a3, bf[nt][0], bf[nt][1]);
            }
        }
        if (more) sttile(p ^ 1);
    }

#pragma unroll
    for (int mt = 0; mt < 2; mt++) {
        const int r0 = bm + wm * 32 + mt * 16 + gid;
        const int r1 = r0 + 8;
#pragma unroll
        for (int nt = 0; nt < 8; nt++) {
            const int n = bn + wn * 64 + nt * 8 + tg * 2;
            float2 v0 = make_float2(acc[mt][nt][0], acc[mt][nt][1]);
            float2 v1 = make_float2(acc[mt][nt][2], acc[mt][nt][3]);
            if (bias) {
                float b0 = bias[n], b1 = bias[n + 1];
                v0.x += b0; v0.y += b1;
                v1.x += b0; v1.y += b1;
            }
            if (r0 < M) {
                float2 o = v0;
                if (addm) {
                    const float2 ad = *(const float2*)(addm + (size_t)r0 * ldadd + n);
                    o.x += ad.x; o.y += ad.y;
                }
                if (C)  *(float2*)(C + (size_t)r0 * ldc + n) = o;
                if (C2) *(float2*)(C2 + (size_t)r0 * ldc + n) = o;
                if (Ch) *(__nv_bfloat162*)(Ch + (size_t)r0 * ldc + n) =
                            __floats2bfloat162_rn(o.x, o.y);
            }
            if (r1 < M) {
                float2 o = v1;
                if (addm) {
                    const float2 ad = *(const float2*)(addm + (size_t)r1 * ldadd + n);
                    o.x += ad.x; o.y += ad.y;
                }
                if (C)  *(float2*)(C + (size_t)r1 * ldc + n) = o;
                if (C2) *(float2*)(C2 + (size_t)r1 * ldc + n) = o;
                if (Ch) *(__nv_bfloat162*)(Ch + (size_t)r1 * ldc + n) =
                            __floats2bfloat162_rn(o.x, o.y);
            }
        }
    }
}

// ---------------- weight precompute (exact fp32) -----------------------------
__global__ void wz_kernel(const float* __restrict__ gatW, const float* __restrict__ fcW,
                          float* __restrict__ Wz3, float* __restrict__ Wzc) {
    int p = blockIdx.y;
    int k = blockIdx.x;
    int n = threadIdx.x;
    const float* Wrow = gatW + ((size_t)p * DD + k) * HD;
    const float* F = fcW + (size_t)p * HD * DD;
    __shared__ float wr[HD];
    for (int i = n; i < HD; i += DD) wr[i] = Wrow[i];
    __syncthreads();
    float a0 = 0.f, a1 = 0.f, a2 = 0.f;
    for (int d = 0; d < DD; d++) {
        a0 += wr[d]          * F[(size_t)d * DD + n];
        a1 += wr[DD + d]     * F[(size_t)(DD + d) * DD + n];
        a2 += wr[2 * DD + d] * F[(size_t)(2 * DD + d) * DD + n];
    }
    size_t o = ((size_t)p * DD + k) * HD;
    Wz3[o + n] = a0; Wz3[o + DD + n] = a1; Wz3[o + 2 * DD + n] = a2;
    Wzc[((size_t)p * DD + k) * DD + n] = a0 + a1 + a2;
}

__global__ void wlr_kernel(const float* __restrict__ gatW, const float* __restrict__ al,
                           const float* __restrict__ ar, float* __restrict__ Wlr) {
    int p = blockIdx.x;
    int k = threadIdx.x;
    __shared__ float sal[HD], sar[HD];
    for (int i = k; i < HD; i += DD) {
        sal[i] = al[(size_t)p * HD + i];
        sar[i] = ar[(size_t)p * HD + i];
    }
    __syncthreads();
    const float* Wrow = gatW + ((size_t)p * DD + k) * HD;
    float o[6] = {0.f, 0.f, 0.f, 0.f, 0.f, 0.f};
    for (int h = 0; h < 3; h++)
        for (int d = 0; d < DD; d++) {
            float w = Wrow[h * DD + d];
            o[h]     += w * sal[h * DD + d];
            o[3 + h] += w * sar[h * DD + d];
        }
#pragma unroll
    for (int i = 0; i < 6; i++) Wlr[((size_t)p * DD + k) * 8 + i] = o[i];
}

__global__ void bz_kernel(const float* __restrict__ gb, const float* __restrict__ fcW,
                          const float* __restrict__ fcb, float* __restrict__ bz) {
    int p = blockIdx.x, n = threadIdx.x;
    const float* g = gb + (size_t)p * HD;
    const float* W = fcW + (size_t)p * HD * DD;
    float s = fcb[(size_t)p * DD + n];
    for (int k = 0; k < HD; k++) s += g[k] * W[(size_t)k * DD + n];
    bz[(size_t)p * DD + n] = s;
}

// ---------------- small batched kernels ---------------------------------------
__global__ void zero_int(int* p, int n) {
    int i = blockIdx.x * blockDim.x + threadIdx.x;
    if (i < n) p[i] = 0;
}
__global__ void build_adj_b(ADJB g) {
    int z = blockIdx.y;
    int i = blockIdx.x * blockDim.x + threadIdx.x;
    if (i >= g.ecnt[z]) return;
    int d = g.dst[z][i];
    if (d < EXER_N) return;
    int dl = d - EXER_N;
    int slot = atomicAdd(&g.cnt[z][dl], 1);
    if (slot < CAP) g.adj[z][(size_t)dl * CAP + slot] = g.src[z][i];
}

// fused exer-side escore + zlzr: 8 warp reductions per node
__global__ void ezl_b(EZB g) {
    int z = blockIdx.y;
    int n = blockIdx.x, t = threadIdx.x;
    float xv = g.x[z][(size_t)n * DD + t];
    float zv = g.z[z][(size_t)n * DD + t];
    const float* w = g.wlr[z] + (size_t)t * 8;
    const float* aw = g.aW[z];
    float o[8];
#pragma unroll
    for (int i = 0; i < 6; i++) o[i] = xv * w[i];
    o[6] = zv * aw[t];
    o[7] = zv * aw[DD + t];
#pragma unroll
    for (int off = 16; off; off >>= 1)
#pragma unroll
        for (int i = 0; i < 8; i++) o[i] += __shfl_xor_sync(0xffffffffu, o[i], off);
    __shared__ float red[4][8];
    int wp = t >> 5;
    if ((t & 31) == 0)
#pragma unroll
        for (int i = 0; i < 8; i++) red[wp][i] = o[i];
    __syncthreads();
    if (t < 8) {
        float v = red[0][t] + red[1][t] + red[2][t] + red[3][t];
        if (t < 3)       g.el[z][(size_t)n * 4 + t] = v;
        else if (t < 6)  g.er[z][(size_t)n * 4 + (t - 3)] = v;
        else if (t == 6) g.zl[z][n] = v;
        else             g.zr[z][n] = v;
    }
}

// ---------------- fully fused GAT (single branch), 2 dst/block ---------------
__global__ __launch_bounds__(256)
void gat_fused_b(FZB g, int ldo) {
    const int z = blockIdx.y;
    const int t = threadIdx.x;
    const int hh = t >> 7;                 // half 0/1 -> dst
    const int tt = t & 127;                // lane within half
    const int dl = blockIdx.x * 2 + hh;
    const int ww = tt >> 5, lane = t & 31;

    __shared__ int   ssrc[2][CAP];
    __shared__ float se[2][CAP * 3];
    __shared__ float se2[2][CAP];
    __shared__ float red[2][4][6];
    __shared__ float sm[2][3], ssum[2][3];
    __shared__ float sm2[2], ssm2[2];

    int deg = g.cnt[z][dl]; if (deg > CAP) deg = CAP;

    float xv = g.x[z][(size_t)dl * DD + tt];
    {
        const float* wl = g.wlr[z] + (size_t)tt * 8;
        float o[6];
#pragma unroll
        for (int i = 0; i < 6; i++) o[i] = xv * wl[i];
#pragma unroll
        for (int off = 16; off; off >>= 1)
#pragma unroll
            for (int i = 0; i < 6; i++) o[i] += __shfl_xor_sync(0xffffffffu, o[i], off);
        if (lane == 0)
#pragma unroll
            for (int i = 0; i < 6; i++) red[hh][ww][i] = o[i];
    }
    __syncthreads();
    float elS[3], erS[3];
#pragma unroll
    for (int h = 0; h < 3; h++) {
        elS[h] = red[hh][0][h] + red[hh][1][h] + red[hh][2][h] + red[hh][3][h];
        erS[h] = red[hh][0][3 + h] + red[hh][1][3 + h] + red[hh][2][3 + h] + red[hh][3][3 + h];
    }

    if (tt < deg) {
        int s = g.adj[z][(size_t)dl * CAP + tt];
        ssrc[hh][tt] = s;
        float e[3];
        if (s < EXER_N) {
            const float* el = g.elE[z] + (size_t)s * 4;
#pragma unroll
            for (int h = 0; h < 3; h++) e[h] = el[h] + erS[h];
        } else {
#pragma unroll
            for (int h = 0; h < 3; h++) e[h] = elS[h] + erS[h];
        }
#pragma unroll
        for (int h = 0; h < 3; h++)
            se[hh][tt * 3 + h] = e[h] > 0.f ? e[h] : 0.2f * e[h];
    }
    __syncthreads();

    if (ww < 3) {
        float m = -3.0e38f;
        for (int j = lane; j < deg; j += 32) m = fmaxf(m, se[hh][j * 3 + ww]);
#pragma unroll
        for (int off = 16; off; off >>= 1) m = fmaxf(m, __shfl_xor_sync(0xffffffffu, m, off));
        float s = 0.f;
        for (int j = lane; j < deg; j += 32) s += expf(se[hh][j * 3 + ww] - m);
#pragma unroll
        for (int off = 16; off; off >>= 1) s += __shfl_xor_sync(0xffffffffu, s, off);
        if (lane == 0) { sm[hh][ww] = m; ssum[hh][ww] = s; }
    }
    __syncthreads();
    if (tt < deg) {
#pragma unroll
        for (int h = 0; h < 3; h++)
            se[hh][tt * 3 + h] = expf(se[hh][tt * 3 + h] - sm[hh][h]) / ssum[hh][h];
    }
    __syncthreads();

    const __nv_bfloat16* zE3 = g.zE3[z];
    const float* zS3row = g.zS3[z] + (size_t)dl * HD;
    const float sv0 = zS3row[tt], sv1 = zS3row[DD + tt], sv2 = zS3row[2 * DD + tt];
    float acc = 0.f;
    for (int j = 0; j < deg; j++) {
        int s = ssrc[hh][j];
        float v0, v1, v2;
        if (s < EXER_N) {
            const __nv_bfloat16* b = zE3 + (size_t)s * HD;
            v0 = __bfloat162float(b[tt]);
            v1 = __bfloat162float(b[DD + tt]);
            v2 = __bfloat162float(b[2 * DD + tt]);
        } else { v0 = sv0; v1 = sv1; v2 = sv2; }
        acc += se[hh][j * 3 + 0] * v0 + se[hh][j * 3 + 1] * v1 + se[hh][j * 3 + 2] * v2;
    }
    const float zval = acc + g.bz[z][tt];

    {
        const float* aw = g.aW[z];
        float a = zval * aw[tt];
        float b = zval * aw[DD + tt];
#pragma unroll
        for (int off = 16; off; off >>= 1) {
            a += __shfl_xor_sync(0xffffffffu, a, off);
            b += __shfl_xor_sync(0xffffffffu, b, off);
        }
        __syncthreads();
        if (lane == 0) { red[hh][ww][0] = a; red[hh][ww][1] = b; }
    }
    __syncthreads();
    const float zlS = red[hh][0][0] + red[hh][1][0] + red[hh][2][0] + red[hh][3][0];
    const float zrS = red[hh][0][1] + red[hh][1][1] + red[hh][2][1] + red[hh][3][1];

    if (tt < deg) {
        int s = ssrc[hh][tt];
        float zl = (s < EXER_N) ? g.zlE[z][s] : zlS;
        se2[hh][tt] = zl + zrS;
    }
    __syncthreads();
    if (ww == 0) {
        float m = -3.0e38f;
        for (int jj = lane; jj < deg; jj += 32) m = fmaxf(m, se2[hh][jj]);
#pragma unroll
        for (int off = 16; off; off >>= 1) m = fmaxf(m, __shfl_xor_sync(0xffffffffu, m, off));
        float s = 0.f;
        for (int jj = lane; jj < deg; jj += 32) s += expf(se2[hh][jj] - m);
#pragma unroll
        for (int off = 16; off; off >>= 1) s += __shfl_xor_sync(0xffffffffu, s, off);
        if (lane == 0) { sm2[hh] = m; ssm2[hh] = s; }
    }
    __syncthreads();
    if (tt < deg) se2[hh][tt] = expf(se2[hh][tt] - sm2[hh]) / ssm2[hh];
    __syncthreads();

    const __nv_bfloat16* zE = g.zE[z];
    float acc2 = 0.f;
    for (int j = 0; j < deg; j++) {
        int s = ssrc[hh][j];
        float v = (s < EXER_N) ? __bfloat162float(zE[(size_t)s * DD + tt]) : zval;
        acc2 += se2[hh][j] * v;
    }
    g.out[z][(size_t)dl * ldo + tt] = acc2;
    if (g.out2[z]) g.out2[z][(size_t)dl * ldo + tt] = acc2;
}

// ---------------- fused GAT merged X/P per slot, 2 dst/block ------------------
__global__ __launch_bounds__(256)
void gat_fused_m(FZM g, int ldo) {
    const int z = blockIdx.y;
    const int t = threadIdx.x;
    const int hh = t >> 7;
    const int tt = t & 127;
    const int dl = blockIdx.x * 2 + hh;
    const int ww = tt >> 5, lane = t & 31;

    __shared__ int   ssrc[2][CAP];
    __shared__ float seX[2][CAP * 3], seP[2][CAP * 3];
    __shared__ float se2X[2][CAP], se2P[2][CAP];
    __shared__ float red[2][4][12];
    __shared__ float smX[2][3], ssumX[2][3], smP[2][3], ssumP[2][3];
    __shared__ float sm2X[2], ssm2X[2], sm2P[2], ssm2P[2];

    int deg = g.cnt[z][dl]; if (deg > CAP) deg = CAP;

    {
        float xvX = g.xX[z][(size_t)dl * DD + tt];
        float xvP = g.xP[z][(size_t)dl * DD + tt];
        const float* wl = g.wlr[z] + (size_t)tt * 8;
        float o[12];
#pragma unroll
        for (int i = 0; i < 6; i++) { o[i] = xvX * wl[i]; o[6 + i] = xvP * wl[i]; }
#pragma unroll
        for (int off = 16; off; off >>= 1)
#pragma unroll
            for (int i = 0; i < 12; i++) o[i] += __shfl_xor_sync(0xffffffffu, o[i], off);
        if (lane == 0)
#pragma unroll
            for (int i = 0; i < 12; i++) red[hh][ww][i] = o[i];
    }
    __syncthreads();
    float elX[3], erX[3], elP[3], erP[3];
#pragma unroll
    for (int h = 0; h < 3; h++) {
        elX[h] = red[hh][0][h] + red[hh][1][h] + red[hh][2][h] + red[hh][3][h];
        erX[h] = red[hh][0][3 + h] + red[hh][1][3 + h] + red[hh][2][3 + h] + red[hh][3][3 + h];
        elP[h] = red[hh][0][6 + h] + red[hh][1][6 + h] + red[hh][2][6 + h] + red[hh][3][6 + h];
        erP[h] = red[hh][0][9 + h] + red[hh][1][9 + h] + red[hh][2][9 + h] + red[hh][3][9 + h];
    }

    if (tt < deg) {
        int s = g.adj[z][(size_t)dl * CAP + tt];
        ssrc[hh][tt] = s;
        float ex[3], ep[3];
        if (s < EXER_N) {
            const float* el = g.elE[z] + (size_t)s * 4;
#pragma unroll
            for (int h = 0; h < 3; h++) { ex[h] = el[h] + erX[h]; ep[h] = el[h] + erP[h]; }
        } else {
#pragma unroll
            for (int h = 0; h < 3; h++) { ex[h] = elX[h] + erX[h]; ep[h] = elP[h] + erP[h]; }
        }
#pragma unroll
        for (int h = 0; h < 3; h++) {
            seX[hh][tt * 3 + h] = ex[h] > 0.f ? ex[h] : 0.2f * ex[h];
            seP[hh][tt * 3 + h] = ep[h] > 0.f ? ep[h] : 0.2f * ep[h];
        }
    }
    __syncthreads();

    if (ww < 3) {
        float mX = -3.0e38f, mP = -3.0e38f;
        for (int j = lane; j < deg; j += 32) {
            mX = fmaxf(mX, seX[hh][j * 3 + ww]);
            mP = fmaxf(mP, seP[hh][j * 3 + ww]);
        }
#pragma unroll
        for (int off = 16; off; off >>= 1) {
            mX = fmaxf(mX, __shfl_xor_sync(0xffffffffu, mX, off));
            mP = fmaxf(mP, __shfl_xor_sync(0xffffffffu, mP, off));
        }
        float sX = 0.f, sP = 0.f;
        for (int j = lane; j < deg; j += 32) {
            sX += expf(seX[hh][j * 3 + ww] - mX);
            sP += expf(seP[hh][j * 3 + ww] - mP);
        }
#pragma unroll
        for (int off = 16; off; off >>= 1) {
            sX += __shfl_xor_sync(0xffffffffu, sX, off);
            sP += __shfl_xor_sync(0xffffffffu, sP, off);
        }
        if (lane == 0) {
            smX[hh][ww] = mX; ssumX[hh][ww] = sX;
            smP[hh][ww] = mP; ssumP[hh][ww] = sP;
        }
    }
    __syncthreads();
    if (tt < deg) {
#pragma unroll
        for (int h = 0; h < 3; h++) {
            seX[hh][tt * 3 + h] = expf(seX[hh][tt * 3 + h] - smX[hh][h]) / ssumX[hh][h];
            seP[hh][tt * 3 + h] = expf(seP[hh][tt * 3 + h] - smP[hh][h]) / ssumP[hh][h];
        }
    }
    __syncthreads();

    const __nv_bfloat16* zE3 = g.zE3[z];
    const float* zX3 = g.zS3X[z] + (size_t)dl * HD;
    const float* zP3 = g.zS3P[z] + (size_t)dl * HD;
    const float xs0 = zX3[tt], xs1 = zX3[DD + tt], xs2 = zX3[2 * DD + tt];
    const float ps0 = zP3[tt], ps1 = zP3[DD + tt], ps2 = zP3[2 * DD + tt];
    float accX = 0.f, accP = 0.f;
    for (int j = 0; j < deg; j++) {
        int s = ssrc[hh][j];
        float wx0 = seX[hh][j * 3 + 0], wx1 = seX[hh][j * 3 + 1], wx2 = seX[hh][j * 3 + 2];
        float wp0 = seP[hh][j * 3 + 0], wp1 = seP[hh][j * 3 + 1], wp2 = seP[hh][j * 3 + 2];
        if (s < EXER_N) {
            const __nv_bfloat16* b = zE3 + (size_t)s * HD;
            float v0 = __bfloat162float(b[tt]);
            float v1 = __bfloat162float(b[DD + tt]);
            float v2 = __bfloat162float(b[2 * DD + tt]);
            accX += wx0 * v0 + wx1 * v1 + wx2 * v2;
            accP += wp0 * v0 + wp1 * v1 + wp2 * v2;
        } else {
            accX += wx0 * xs0 + wx1 * xs1 + wx2 * xs2;
            accP += wp0 * ps0 + wp1 * ps1 + wp2 * ps2;
        }
    }
    const float bzv = g.bz[z][tt];
    const float zvX = accX + bzv;
    const float zvP = accP + bzv;

    {
        const float* aw = g.aW[z];
        float o[4] = {zvX * aw[tt], zvX * aw[DD + tt], zvP * aw[tt], zvP * aw[DD + tt]};
#pragma unroll
        for (int off = 16; off; off >>= 1)
#pragma unroll
            for (int i = 0; i < 4; i++) o[i] += __shfl_xor_sync(0xffffffffu, o[i], off);
        __syncthreads();
        if (lane == 0)
#pragma unroll
            for (int i = 0; i < 4; i++) red[hh][ww][i] = o[i];
    }
    __syncthreads();
    const float zlX = red[hh][0][0] + red[hh][1][0] + red[hh][2][0] + red[hh][3][0];
    const float zrX = red[hh][0][1] + red[hh][1][1] + red[hh][2][1] + red[hh][3][1];
    const float zlP = red[hh][0][2] + red[hh][1][2] + red[hh][2][2] + red[hh][3][2];
    const float zrP = red[hh][0][3] + red[hh][1][3] + red[hh][2][3] + red[hh][3][3];

    if (tt < deg) {
        int s = ssrc[hh][tt];
        if (s < EXER_N) {
            float zl = g.zlE[z][s];
            se2X[hh][tt] = zl + zrX;
            se2P[hh][tt] = zl + zrP;
        } else {
            se2X[hh][tt] = zlX + zrX;
            se2P[hh][tt] = zlP + zrP;
        }
    }
    __syncthreads();
    if (ww < 2) {
        float* se2 = (ww == 0) ? se2X[hh] : se2P[hh];
        float m = -3.0e38f;
        for (int j2 = lane; j2 < deg; j2 += 32) m = fmaxf(m, se2[j2]);
#pragma unroll
        for (int off = 16; off; off >>= 1) m = fmaxf(m, __shfl_xor_sync(0xffffffffu, m, off));
        float s = 0.f;
        for (int j2 = lane; j2 < deg; j2 += 32) s += expf(se2[j2] - m);
#pragma unroll
        for (int off = 16; off; off >>= 1) s += __shfl_xor_sync(0xffffffffu, s, off);
        if (lane == 0) {
            if (ww == 0) { sm2X[hh] = m; ssm2X[hh] = s; }
            else         { sm2P[hh] = m; ssm2P[hh] = s; }
        }
    }
    __syncthreads();
    if (tt < deg) {
        se2X[hh][tt] = expf(se2X[hh][tt] - sm2X[hh]) / ssm2X[hh];
        se2P[hh][tt] = expf(se2P[hh][tt] - sm2P[hh]) / ssm2P[hh];
    }
    __syncthreads();

    const __nv_bfloat16* zE = g.zE[z];
    float acc2X = 0.f, acc2P = 0.f;
    for (int j = 0; j < deg; j++) {
        int s = ssrc[hh][j];
        if (s < EXER_N) {
            float v = __bfloat162float(zE[(size_t)s * DD + tt]);
            acc2X += se2X[hh][j] * v;
            acc2P += se2P[hh][j] * v;
        } else {
            acc2X += se2X[hh][j] * zvX;
            acc2P += se2P[hh][j] * zvP;
        }
    }
    g.outX[z][(size_t)dl * ldo + tt] = acc2X;
    g.outP[z][(size_t)dl * ldo + tt] = acc2P;
}

// SSL ------------------------------------------------------------------------
__global__ void norm_rows_b(NRB g, const int* __restrict__ ids) {
    int z = blockIdx.y;
    int i = blockIdx.x, t = threadIdx.x;
    int r = ids[i];
    float v = g.emb[z][(size_t)r * DD + t];
    float sq = v * v;
#pragma unroll
    for (int off = 16; off; off >>= 1) sq += __shfl_xor_sync(0xffffffffu, sq, off);
    __shared__ float w4[4];
    if ((t & 31) == 0) w4[t >> 5] = sq;
    __syncthreads();
    float tot = w4[0] + w4[1] + w4[2] + w4[3];
    float nrm = sqrtf(tot);
    g.out[z][(size_t)i * DD + t] = v / fmaxf(nrm, 1e-12f);
}

__global__ void colsum_part(const float* __restrict__ nbp, float* __restrict__ part) {
    int b = blockIdx.x, t = threadIdx.x;
    float s = 0.f;
    const int i0 = b * (BATCH / 16);
#pragma unroll 4
    for (int i = i0; i < i0 + BATCH / 16; i++) s += nbp[(size_t)i * DD + t];
    part[b * DD + t] = s;
}
__global__ void colsum_fin(const float* __restrict__ part, float* __restrict__ S) {
    int t = threadIdx.x;
    float s = 0.f;
#pragma unroll
    for (int b = 0; b < 16; b++) s += part[b * DD + t];
    S[t] = s;
}

__global__ void loss_part(const float* __restrict__ nb, const float* __restrict__ nbp,
                          const float* __restrict__ S, float* __restrict__ lp) {
    const int w = threadIdx.x >> 5, lane = threadIdx.x & 31;
    const int i = blockIdx.x * 8 + w;
    const float4 xv = *(const float4*)(nb  + (size_t)i * DD + lane * 4);
    const float4 yv = *(const float4*)(nbp + (size_t)i * DD + lane * 4);
    const float4 sv = *(const float4*)(S + lane * 4);
    float dg = xv.x * yv.x + xv.y * yv.y + xv.z * yv.z + xv.w * yv.w;
    float rs = xv.x * sv.x + xv.y * sv.y + xv.z * sv.z + xv.w * sv.w;
#pragma unroll
    for (int off = 16; off; off >>= 1) {
        dg += __shfl_xor_sync(0xffffffffu, dg, off);
        rs += __shfl_xor_sync(0xffffffffu, rs, off);
    }
    if (lane == 0) {
        float divided = expf(dg * 5.0f) / (rs * 5.0f + 1e-8f);
        lp[i] = -logf(fmaxf(divided, 1e-8f));
    }
}
__global__ void loss_fin(const float* __restrict__ lp, float* __restrict__ out) {
    int t = threadIdx.x;
    float s = 0.f;
#pragma unroll
    for (int k = 0; k < BATCH / 256; k++) s += lp[t + k * 256];
    __shared__ float red[256];
    red[t] = s;
    __syncthreads();
    for (int st = 128; st; st >>= 1) { if (t < st) red[t] += red[t + st]; __syncthreads(); }
    if (t == 0) out[0] = red[0];
}

// ---------------- host orchestration ------------------------------------------
extern "C" void kernel_launch(void* const* d_in, const int* in_sizes, int n_in,
                              void* d_out_, int out_size)
{
    const float* stu_table  = (const float*)d_in[0];
    const float* exer_table = (const float*)d_in[1];
    const float* gat_W  = (const float*)d_in[2];
    const float* attn_l = (const float*)d_in[3];
    const float* attn_r = (const float*)d_in[4];
    const float* gat_b  = (const float*)d_in[5];
    const float* fc_W   = (const float*)d_in[6];
    const float* fc_b   = (const float*)d_in[7];
    const float* aW     = (const float*)d_in[8];
    const float* f1W    = (const float*)d_in[9];
    const float* f1b    = (const float*)d_in[10];
    const float* f2W    = (const float*)d_in[11];
    const float* f2b    = (const float*)d_in[12];
    const int* e_src[3] = {(const int*)d_in[13], (const int*)d_in[15], (const int*)d_in[21]};
    const int* e_dst[3] = {(const int*)d_in[14], (const int*)d_in[16], (const int*)d_in[22]};
    int e_n[3] = {in_sizes[13], in_sizes[15], in_sizes[21]};
    const int* stu_id = (const int*)d_in[23];
    float* d_out = (float*)d_out_;
    (void)n_in;

    float* FA = nullptr; int* IA = nullptr; __nv_bfloat16* HA = nullptr;
    cudaGetSymbolAddress((void**)&FA, g_farena);
    cudaGetSymbolAddress((void**)&IA, g_iarena);
    cudaGetSymbolAddress((void**)&HA, g_harena);

    float* Wz3   = FA + O_Wz3;
    float* Wzc   = FA + O_Wzc;
    float* Wlr   = FA + O_Wlr;
    float* bz    = FA + O_bz;
    float* zE    = FA + O_zE;
    float* elE   = FA + O_elE;
    float* zlE   = FA + O_zlE;
    float* erD   = FA + O_erD;
    float* zrD   = FA + O_zrD;
    float* ABCD  = FA + O_ABCD;
    float* ABPCD = FA + O_ABPCD;
    float* stu1  = FA + O_stu1;
    float* stu1p = FA + O_stu1p;
    float* XYX   = FA + O_XYX;
    float* XYP   = FA + O_XYP;
    float* stu2  = FA + O_stu2;
    float* stu2p = FA + O_stu2p;
    float* nb    = FA + O_nb;
    float* nbp   = FA + O_nbp;
    float* Sv    = FA + O_S;
    float* lossD = FA + O_lossd;
    float* partV = FA + O_part;
    float* lpart = FA + O_lpart;
    __nv_bfloat16* zE3h = HA + OH_zE3;
    __nv_bfloat16* zEh  = HA + OH_zE;

    const int pidx[3] = {0, 1, 4};
    const int gM_E = (EXER_N + 127) / 128;
    const int gM_S = (STU_N + 127) / 128;

    auto scr  = [&](int sc, size_t off) { return FA + O_SCR + (size_t)sc * SC_TOT + off; };
    auto adjP = [&](int s) { return IA + OI_adj + (size_t)s * STU_N * CAP; };
    auto cntP = [&](int s) { return IA + OI_cnt + (size_t)s * STU_N; };

    // ---- weight precompute + adjacency ----
    wz_kernel<<<dim3(DD, 5), DD>>>(gat_W, fc_W, Wz3, Wzc);
    wlr_kernel<<<5, DD>>>(gat_W, attn_l, attn_r, Wlr);
    bz_kernel<<<5, DD>>>(gat_b, fc_W, fc_b, bz);
    zero_int<<<(3 * STU_N + 255) / 256, 256>>>(IA + OI_cnt, 3 * STU_N);
    {
        ADJB g{};
        int max_e = 0;
        for (int s = 0; s < 3; s++) {
            g.src[s] = e_src[s]; g.dst[s] = e_dst[s]; g.ecnt[s] = e_n[s];
            g.adj[s] = adjP(s);  g.cnt[s] = cntP(s);
            if (e_n[s] > max_e) max_e = e_n[s];
        }
        build_adj_b<<<dim3((max_e + 255) / 256, 3), 256>>>(g);
    }

    // ---- phase A: exer-side invariants ----
    {
        GB g{};
        for (int s = 0; s < 3; s++) {
            g.A[s] = exer_table;
            g.B[s] = Wz3 + (size_t)pidx[s] * DD * HD;
            g.Ch[s] = zE3h + (size_t)s * EXER_N * HD;
        }
        tgemm_b<<<dim3(HD / 128, gM_E, 3), 256>>>(g, DD, HD, 0, EXER_N, HD, DD);
    }
    {
        GB g{};
        for (int s = 0; s < 3; s++) {
            g.A[s] = exer_table;
            g.B[s] = Wzc + (size_t)pidx[s] * DD * DD;
            g.C[s] = zE + (size_t)s * EXER_N * DD;
            g.Ch[s] = zEh + (size_t)s * EXER_N * DD;
            g.bias[s] = bz + (size_t)pidx[s] * DD;
        }
        tgemm_b<<<dim3(1, gM_E, 3), 256>>>(g, DD, DD, 0, EXER_N, DD, DD);
    }
    {
        EZB g{};
        for (int s = 0; s < 3; s++) {
            g.x[s]   = exer_table;
            g.wlr[s] = Wlr + (size_t)pidx[s] * DD * 8;
            g.z[s]   = zE + (size_t)s * EXER_N * DD;
            g.aW[s]  = aW + (size_t)pidx[s] * 2 * DD;
            g.el[s]  = elE + (size_t)s * EXER_N * 4;
            g.er[s]  = erD;
            g.zl[s]  = zlE + (size_t)s * EXER_N;
            g.zr[s]  = zrD;
        }
        ezl_b<<<dim3(EXER_N, 3), 128>>>(g);
    }

    // ---- layers 2,3: single GEMM, dual-store ----
    {
        GB g{};
        for (int i = 0; i < 2; i++) {
            int coff = (i == 0) ? 2 * DD : 3 * DD;
            g.A[i] = stu_table;
            g.B[i] = Wzc + (size_t)(2 + i) * DD * DD;
            g.C[i] = ABCD + coff;
            g.C2[i] = ABPCD + coff;
            g.bias[i] = bz + (size_t)(2 + i) * DD;
        }
        tgemm_b<<<dim3(1, gM_S, 2), 256>>>(g, DD, 4 * DD, 0, STU_N, DD, DD);
    }

    // ---- phase B: zS3 GEMM + one fused GAT launch (2 dst/block, z=3) ----
    {
        const int slot[3] = {0, 1, 2};
        {
            GB g{};
            for (int i = 0; i < 3; i++) {
                g.A[i] = stu_table;
                g.B[i] = Wz3 + (size_t)pidx[slot[i]] * DD * HD;
                g.C[i] = scr(i, SC_zS3);
            }
            tgemm_b<<<dim3(HD / 128, gM_S, 3), 256>>>(g, DD, HD, 0, STU_N, HD, DD);
        }
        {
            FZB g{};
            float* outb[3]  = {ABCD, ABCD + DD, ABPCD + DD};
            float* outb2[3] = {ABPCD, nullptr, nullptr};
            for (int i = 0; i < 3; i++) {
                int s = slot[i];
                g.adj[i] = adjP(s); g.cnt[i] = cntP(s);
                g.x[i]   = stu_table;
                g.wlr[i] = Wlr + (size_t)pidx[s] * DD * 8;
                g.elE[i] = elE + (size_t)s * EXER_N * 4;
                g.zE3[i] = zE3h + (size_t)s * EXER_N * HD;
                g.zS3[i] = scr(i, SC_zS3);
                g.zE[i]  = zEh + (size_t)s * EXER_N * DD;
                g.zlE[i] = zlE + (size_t)s * EXER_N;
                g.bz[i]  = bz + (size_t)pidx[s] * DD;
                g.aW[i]  = aW + (size_t)pidx[s] * 2 * DD;
                g.out[i]  = outb[i];
                g.out2[i] = outb2[i];
            }
            gat_fused_b<<<dim3(STU_N / 2, 3), 256>>>(g, 4 * DD);
        }
    }

    // ---- fuse1: K=512 GEMM + residual ----
    {
        GB g{};
        g.A[0] = ABCD;  g.C[0] = stu1;  g.bias[0] = f1b; g.addm[0] = stu_table;
        g.A[1] = ABPCD; g.C[1] = stu1p; g.bias[1] = f1b; g.addm[1] = stu_table;
        g.B[0] = f1W; g.B[1] = f1W;
        tgemm_b<<<dim3(1, gM_S, 2), 256>>>(g, 4 * DD, DD, DD, STU_N, DD, 4 * DD);
    }

    // ---- phase D: zS3 GEMM (z=4) + one merged fused GAT (2 dst/block, z=2) --
    {
        const float* xS[4] = {stu1, stu1, stu1p, stu1p};
        const int slot4[4] = {0, 1, 0, 1};
        {
            GB g{};
            for (int i = 0; i < 4; i++) {
                g.A[i] = xS[i];
                g.B[i] = Wz3 + (size_t)pidx[slot4[i]] * DD * HD;
                g.C[i] = scr(i, SC_zS3);
            }
            tgemm_b<<<dim3(HD / 128, gM_S, 4), 256>>>(g, DD, HD, 0, STU_N, HD, DD);
        }
        {
            FZM g{};
            for (int s = 0; s < 2; s++) {
                g.adj[s] = adjP(s); g.cnt[s] = cntP(s);
                g.wlr[s] = Wlr + (size_t)pidx[s] * DD * 8;
                g.elE[s] = elE + (size_t)s * EXER_N * 4;
                g.zE3[s] = zE3h + (size_t)s * EXER_N * HD;
                g.zE[s]  = zEh + (size_t)s * EXER_N * DD;
                g.zlE[s] = zlE + (size_t)s * EXER_N;
                g.bz[s]  = bz + (size_t)pidx[s] * DD;
                g.aW[s]  = aW + (size_t)pidx[s] * 2 * DD;
                g.xX[s]  = stu1;  g.xP[s] = stu1p;
                g.zS3X[s] = scr(s, SC_zS3);
                g.zS3P[s] = scr(s + 2, SC_zS3);
                g.outX[s] = XYX + (size_t)s * DD;
                g.outP[s] = XYP + (size_t)s * DD;
            }
            gat_fused_m<<<dim3(STU_N / 2, 2), 256>>>(g, 2 * DD);
        }
    }

    // ---- fusion2: K=256 + residual; stu2 dual-stored to d_out ----
    const int NOUT = STU_N * DD;
    {
        GB g{};
        g.A[0] = XYX; g.C[0] = stu2;  g.bias[0] = f2b; g.addm[0] = stu1;
        g.A[1] = XYP; g.C[1] = stu2p; g.bias[1] = f2b; g.addm[1] = stu1p;
        g.B[0] = f2W; g.B[1] = f2W;
        if (out_size >= NOUT) g.C2[0] = d_out;
        tgemm_b<<<dim3(1, gM_S, 2), 256>>>(g, 2 * DD, DD, DD, STU_N, DD, 2 * DD);
    }

    float* lossdst = lossD;
    if (out_size == 1) lossdst = d_out;
    else if (out_size > NOUT) lossdst = d_out + (out_size - 1);

    {
        NRB g{};
        g.emb[0] = stu2;  g.out[0] = nb;
        g.emb[1] = stu2p; g.out[1] = nbp;
        norm_rows_b<<<dim3(BATCH, 2), 128>>>(g, stu_id);
    }
    colsum_part<<<16, 128>>>(nbp, partV);
    colsum_fin<<<1, 128>>>(partV, Sv);
    loss_part<<<BATCH / 8, 256>>>(nb, nbp, Sv, lpart);
    loss_fin<<<1, 256>>>(lpart, lossdst);
}